// round 14
// baseline (speedup 1.0000x reference)
#include <cuda_runtime.h>
#include <cuda_fp16.h>
#include <cstdint>

#define DD 128
#define ROWS_ITER 256        // rows per CTA iteration (16 per warp)
#define ITERS 4              // iterations per CTA -> 1024 rows/CTA
#define NTHREADS 512

// ---- smem byte offsets ----
#define SM_B1   0            // GEMM1 B: uint4 {bh0,bh1,bl0,bl1} f16x2 frags (64KB)
#define SM_B2   65536        // GEMM2 B: uint2 {b0,b1} f16x2 (iscl*R) frags (32KB)
#define SM_ZL   98304        // z lo-parts, thread-private: 16 warps x 4KB (64KB)
#define SM_SCL  163840       // 128 f32
#define SMEM_BYTES 164352

// D += A(f16) * B(f16), m16n8k16, fp32 accumulate
__device__ __forceinline__ void mma16(float d[4], const uint32_t a[4],
                                      uint32_t b0, uint32_t b1) {
    asm volatile(
        "mma.sync.aligned.m16n8k16.row.col.f32.f16.f16.f32 "
        "{%0,%1,%2,%3}, {%4,%5,%6,%7}, {%8,%9}, {%0,%1,%2,%3};"
        : "+f"(d[0]), "+f"(d[1]), "+f"(d[2]), "+f"(d[3])
        : "r"(a[0]), "r"(a[1]), "r"(a[2]), "r"(a[3]), "r"(b0), "r"(b1));
}

__device__ __forceinline__ uint32_t h2pack(float a, float b) {
    __half2 h = __floats2half2_rn(a, b);
    return *(uint32_t*)&h;
}
__device__ __forceinline__ float2 h2unpack(uint32_t u) {
    __half2 h = *(__half2*)&u;
    return __half22float2(h);
}

extern "C" __global__ void __launch_bounds__(NTHREADS, 1)
rotadapt_mma_kernel(const float* __restrict__ k,
                    const float* __restrict__ rot,
                    const float* __restrict__ scales,
                    const float* __restrict__ cent,
                    float* __restrict__ out)
{
    extern __shared__ char sb[];
    float* sclp = (float*)(sb + SM_SCL);

    const int tid  = threadIdx.x;
    const int lane = tid & 31, w = tid >> 5;      // 16 warps
    const int g = lane >> 2, t = lane & 3;
    const int rA = 16 * w + g;                    // warp owns rows [16w, 16w+16)

    // ---- prologue: build f16 fragment tables ----
    // u = (ks16*16 + nt)*32 + lane ; n = 8*nt + g', c = 16*ks16 + 2*t'
    // B1 (GEMM1, B[kk][n] = R[n][kk]) hi/lo split
    // B2 (GEMM2, B[kk][n] = iscl[kk]*R[kk][n]) f16 (iscl folded in)
    for (int u = tid; u < 8 * 16 * 32; u += NTHREADS) {
        int ln = u & 31, nt = (u >> 5) & 15, ks = u >> 9;
        int gg = ln >> 2, t2 = ln & 3;
        int n = 8 * nt + gg;
        int c = 16 * ks + 2 * t2;
        float r0 = rot[n * DD + c],     r1 = rot[n * DD + c + 1];
        float r2 = rot[n * DD + c + 8], r3 = rot[n * DD + c + 9];
        uint32_t bh0 = h2pack(r0, r1);
        uint32_t bh1 = h2pack(r2, r3);
        float2 h01 = h2unpack(bh0);
        float2 h23 = h2unpack(bh1);
        uint32_t bl0 = h2pack(r0 - h01.x, r1 - h01.y);
        uint32_t bl1 = h2pack(r2 - h23.x, r3 - h23.y);
        ((uint4*)(sb + SM_B1))[u] = make_uint4(bh0, bh1, bl0, bl1);
        float is0 = 1.0f / fmaxf(scales[c],     1e-6f);
        float is1 = 1.0f / fmaxf(scales[c + 1], 1e-6f);
        float is8 = 1.0f / fmaxf(scales[c + 8], 1e-6f);
        float is9 = 1.0f / fmaxf(scales[c + 9], 1e-6f);
        uint32_t c0p = h2pack(is0 * rot[c * DD + n], is1 * rot[(c + 1) * DD + n]);
        uint32_t c1p = h2pack(is8 * rot[(c + 8) * DD + n], is9 * rot[(c + 9) * DD + n]);
        ((uint2*)(sb + SM_B2))[u] = make_uint2(c0p, c1p);
    }
    if (tid < DD) sclp[tid] = scales[tid];

    float bn[7];
    #pragma unroll
    for (int q = 0; q < 7; ++q) bn[q] = 0.5f * (cent[q] + cent[q + 1]);
    // packed centroid: low16 = f16(cent), high16 = f16(cent - hi)
    uint32_t centpk[8];
    #pragma unroll
    for (int q = 0; q < 8; ++q) {
        float cv = cent[q];
        __half ch = __float2half_rn(cv);
        __half cl = __float2half_rn(cv - __half2float(ch));
        centpk[q] = ((uint32_t)__half_as_ushort(cl) << 16) | __half_as_ushort(ch);
    }

    __syncthreads();   // the ONLY block barrier: B tables + scales ready

    const uint4* b1q = (const uint4*)(sb + SM_B1);
    const uint2* b2q = (const uint2*)(sb + SM_B2);
    // thread-private zl slots: warp block 4KB, lane*8, nt stride 256B
    uint2* zlp = (uint2*)(sb + SM_ZL + w * 4096 + lane * 8);

    const long ctabase = (long)blockIdx.x * (ROWS_ITER * ITERS);

    for (int tt = 0; tt < ITERS; ++tt) {
        const long rowbase = ctabase + (long)tt * ROWS_ITER;

        // ---- GEMM1 (hi/lo fp16, 3 MMAs per k16 step) on RAW k ----
        float acc[16][4];
        #pragma unroll
        for (int nt = 0; nt < 16; ++nt)
            #pragma unroll
            for (int p = 0; p < 4; ++p) acc[nt][p] = 0.0f;

        {
            const float* k0 = k + (rowbase + rA) * (long)DD;
            const float* k1 = k0 + 8 * DD;

            #pragma unroll 2
            for (int ks = 0; ks < 8; ++ks) {
                int c0 = 16 * ks + 2 * t;
                float2 v00 = *(const float2*)&k0[c0];
                float2 v10 = *(const float2*)&k1[c0];
                float2 v08 = *(const float2*)&k0[c0 + 8];
                float2 v18 = *(const float2*)&k1[c0 + 8];
                uint32_t ah[4], al[4];
                ah[0] = h2pack(v00.x, v00.y);
                ah[1] = h2pack(v10.x, v10.y);
                ah[2] = h2pack(v08.x, v08.y);
                ah[3] = h2pack(v18.x, v18.y);
                float2 h0 = h2unpack(ah[0]), h1 = h2unpack(ah[1]);
                float2 h2 = h2unpack(ah[2]), h3 = h2unpack(ah[3]);
                al[0] = h2pack(v00.x - h0.x, v00.y - h0.y);
                al[1] = h2pack(v10.x - h1.x, v10.y - h1.y);
                al[2] = h2pack(v08.x - h2.x, v08.y - h2.y);
                al[3] = h2pack(v18.x - h3.x, v18.y - h3.y);

                uint4 bb[2][4];
                #pragma unroll
                for (int j = 0; j < 4; ++j)
                    bb[0][j] = b1q[(ks * 16 + j) * 32 + lane];
                #pragma unroll
                for (int grp = 0; grp < 4; ++grp) {
                    const int cur = grp & 1, nxt = cur ^ 1;
                    if (grp < 3) {
                        #pragma unroll
                        for (int j = 0; j < 4; ++j)
                            bb[nxt][j] = b1q[(ks * 16 + (grp + 1) * 4 + j) * 32 + lane];
                    }
                    #pragma unroll
                    for (int j = 0; j < 4; ++j) {
                        int nt = grp * 4 + j;
                        mma16(acc[nt], ah, bb[cur][j].x, bb[cur][j].y);   // hi*hi
                        mma16(acc[nt], al, bb[cur][j].x, bb[cur][j].y);   // lo*hi
                        mma16(acc[nt], ah, bb[cur][j].z, bb[cur][j].w);   // hi*lo
                    }
                }
            }
        }

        // ---- norms from acc: R orthogonal => ||k @ R^T|| = ||k|| ----
        float nrm0, nrm1, inv0, inv1;
        {
            float ssq0 = 0.0f, ssq1 = 0.0f;
            #pragma unroll
            for (int nt = 0; nt < 16; ++nt) {
                ssq0 += acc[nt][0] * acc[nt][0] + acc[nt][1] * acc[nt][1];
                ssq1 += acc[nt][2] * acc[nt][2] + acc[nt][3] * acc[nt][3];
            }
            ssq0 += __shfl_xor_sync(0xffffffffu, ssq0, 1);
            ssq0 += __shfl_xor_sync(0xffffffffu, ssq0, 2);
            ssq1 += __shfl_xor_sync(0xffffffffu, ssq1, 1);
            ssq1 += __shfl_xor_sync(0xffffffffu, ssq1, 2);
            nrm0 = sqrtf(ssq0);
            nrm1 = sqrtf(ssq1);
            inv0 = 1.0f / (nrm0 + 1e-10f);
            inv1 = 1.0f / (nrm1 + 1e-10f);
        }

        // ---- prefetch next iteration's k toward L2 ----
        if (tt + 1 < ITERS) {
            const char* np = (const char*)(k + (rowbase + ROWS_ITER) * (long)DD);
            #pragma unroll
            for (int pf = 0; pf < 2; ++pf)
                asm volatile("prefetch.global.L2 [%0];"
                             :: "l"(np + (pf * NTHREADS + tid) * 128));
        }

        // ---- epilogue 1: bucketize-select packed f16 centroids, in-register ----
        // zh pairs stay in acc[nt][0..1]; zl pairs -> thread-private smem
        {
            const float2* scl2 = (const float2*)(sb + SM_SCL);
            #pragma unroll
            for (int nt = 0; nt < 16; ++nt) {
                float2 sc = scl2[(8 * nt + 2 * t) >> 1];
                float f0 = acc[nt][0] * sc.x * inv0, f1 = acc[nt][1] * sc.y * inv0;
                float f2 = acc[nt][2] * sc.x * inv1, f3 = acc[nt][3] * sc.y * inv1;
                uint32_t z0 = centpk[0], z1 = centpk[0], z2 = centpk[0], z3 = centpk[0];
                #pragma unroll
                for (int q = 0; q < 7; ++q) {
                    z0 = (f0 > bn[q]) ? centpk[q + 1] : z0;
                    z1 = (f1 > bn[q]) ? centpk[q + 1] : z1;
                    z2 = (f2 > bn[q]) ? centpk[q + 1] : z2;
                    z3 = (f3 > bn[q]) ? centpk[q + 1] : z3;
                }
                uint32_t uh01 = __byte_perm(z0, z1, 0x5410);
                uint32_t ul01 = __byte_perm(z0, z1, 0x7632);
                uint32_t uh23 = __byte_perm(z2, z3, 0x5410);
                uint32_t ul23 = __byte_perm(z2, z3, 0x7632);
                acc[nt][0] = __uint_as_float(uh01);
                acc[nt][1] = __uint_as_float(uh23);
                zlp[nt * 32] = make_uint2(ul01, ul23);   // same-thread, no sync needed
            }
        }

        // ---- GEMM2 (zh from acc regs + zl from smem, 2 MMAs per k16 step) ----
        float acc2[16][4];
        #pragma unroll
        for (int nt = 0; nt < 16; ++nt)
            #pragma unroll
            for (int p = 0; p < 4; ++p) acc2[nt][p] = 0.0f;

        {
            #pragma unroll 2
            for (int ks = 0; ks < 8; ++ks) {
                uint32_t zh[4] = {
                    __float_as_uint(acc[2 * ks][0]),     __float_as_uint(acc[2 * ks][1]),
                    __float_as_uint(acc[2 * ks + 1][0]), __float_as_uint(acc[2 * ks + 1][1]) };
                uint2 la = zlp[(2 * ks) * 32];
                uint2 lb = zlp[(2 * ks + 1) * 32];
                uint32_t zl[4] = { la.x, la.y, lb.x, lb.y };

                uint2 cb[2][4];
                #pragma unroll
                for (int j = 0; j < 4; ++j)
                    cb[0][j] = b2q[(ks * 16 + j) * 32 + lane];
                #pragma unroll
                for (int grp = 0; grp < 4; ++grp) {
                    const int cur = grp & 1, nxt = cur ^ 1;
                    if (grp < 3) {
                        #pragma unroll
                        for (int j = 0; j < 4; ++j)
                            cb[nxt][j] = b2q[(ks * 16 + (grp + 1) * 4 + j) * 32 + lane];
                    }
                    #pragma unroll
                    for (int j = 0; j < 4; ++j) {
                        int nt = grp * 4 + j;
                        mma16(acc2[nt], zh, cb[cur][j].x, cb[cur][j].y);
                        mma16(acc2[nt], zl, cb[cur][j].x, cb[cur][j].y);
                    }
                }
            }
        }

        // ---- epilogue 2: x norm, store ----
        {
            float* o0 = out + (rowbase + rA) * (long)DD;
            float* o1 = o0 + 8 * DD;
            #pragma unroll
            for (int nt = 0; nt < 16; ++nt) {
                int c = 8 * nt + 2 * t;
                *(float2*)(o0 + c) = make_float2(acc2[nt][0] * nrm0, acc2[nt][1] * nrm0);
                *(float2*)(o1 + c) = make_float2(acc2[nt][2] * nrm1, acc2[nt][3] * nrm1);
            }
        }
    }
}

extern "C" void kernel_launch(void* const* d_in, const int* in_sizes, int n_in,
                              void* d_out, int out_size) {
    const float* k      = (const float*)d_in[0];
    const float* rot    = (const float*)d_in[1];
    const float* scales = (const float*)d_in[2];
    const float* cent   = (const float*)d_in[3];
    float* out = (float*)d_out;

    int nrows = in_sizes[0] / DD;
    int nblocks = nrows / (ROWS_ITER * ITERS);   // 1048576 / 1024 = 1024

    cudaFuncSetAttribute(rotadapt_mma_kernel,
                         cudaFuncAttributeMaxDynamicSharedMemorySize, SMEM_BYTES);
    rotadapt_mma_kernel<<<nblocks, NTHREADS, SMEM_BYTES>>>(k, rot, scales, cent, out);
}

// round 15
// speedup vs baseline: 1.4516x; 1.4516x over previous
#include <cuda_runtime.h>
#include <cuda_fp16.h>
#include <cstdint>

#define DD 128
#define ROWS_ITER 256        // rows per CTA iteration (32 per warp-pair)
#define ITERS 4              // iterations per CTA -> 1024 rows/CTA
#define NTHREADS 512

// ---- smem byte offsets ----
#define SM_B1   0            // GEMM1 B: uint4 {bh0,bh1,bl0,bl1} f16x2 frags (64KB)
#define SM_B2   65536        // GEMM2 B: uint2 f16x2 (iscl*R) frags (32KB)
#define SM_ZI   98304        // indices: 8 pairs x 32 rows x 132B (33792B)
#define SM_SCL  132096       // 128 f32
#define SMEM_BYTES 132608

// D += A(f16) * B(f16), m16n8k16, fp32 accumulate
__device__ __forceinline__ void mma16(float d[4], const uint32_t a[4],
                                      uint32_t b0, uint32_t b1) {
    asm volatile(
        "mma.sync.aligned.m16n8k16.row.col.f32.f16.f16.f32 "
        "{%0,%1,%2,%3}, {%4,%5,%6,%7}, {%8,%9}, {%0,%1,%2,%3};"
        : "+f"(d[0]), "+f"(d[1]), "+f"(d[2]), "+f"(d[3])
        : "r"(a[0]), "r"(a[1]), "r"(a[2]), "r"(a[3]), "r"(b0), "r"(b1));
}

__device__ __forceinline__ uint32_t h2pack(float a, float b) {
    __half2 h = __floats2half2_rn(a, b);
    return *(uint32_t*)&h;
}
__device__ __forceinline__ float2 h2unpack(uint32_t u) {
    __half2 h = *(__half2*)&u;
    return __half22float2(h);
}

extern "C" __global__ void __launch_bounds__(NTHREADS, 1)
rotadapt_mma_kernel(const float* __restrict__ k,
                    const float* __restrict__ rot,
                    const float* __restrict__ scales,
                    const float* __restrict__ cent,
                    float* __restrict__ out)
{
    extern __shared__ char sb[];
    float* sclp = (float*)(sb + SM_SCL);

    const int tid  = threadIdx.x;
    const int lane = tid & 31, w = tid >> 5;      // 16 warps = 8 pairs
    const int g = lane >> 2, t = lane & 3;
    const int pair = w >> 1, sub = w & 1;
    const int rp = 32 * pair;                     // pair's 32-row block
    const int nbase = 8 * sub;                    // warp's nt half: [nbase, nbase+8)

    // ---- prologue: build f16 fragment tables (same as R12/R13) ----
    for (int u = tid; u < 8 * 16 * 32; u += NTHREADS) {
        int ln = u & 31, nt = (u >> 5) & 15, ks = u >> 9;
        int gg = ln >> 2, t2 = ln & 3;
        int n = 8 * nt + gg;
        int c = 16 * ks + 2 * t2;
        float r0 = rot[n * DD + c],     r1 = rot[n * DD + c + 1];
        float r2 = rot[n * DD + c + 8], r3 = rot[n * DD + c + 9];
        uint32_t bh0 = h2pack(r0, r1);
        uint32_t bh1 = h2pack(r2, r3);
        float2 h01 = h2unpack(bh0);
        float2 h23 = h2unpack(bh1);
        uint32_t bl0 = h2pack(r0 - h01.x, r1 - h01.y);
        uint32_t bl1 = h2pack(r2 - h23.x, r3 - h23.y);
        ((uint4*)(sb + SM_B1))[u] = make_uint4(bh0, bh1, bl0, bl1);
        float is0 = 1.0f / fmaxf(scales[c],     1e-6f);
        float is1 = 1.0f / fmaxf(scales[c + 1], 1e-6f);
        float is8 = 1.0f / fmaxf(scales[c + 8], 1e-6f);
        float is9 = 1.0f / fmaxf(scales[c + 9], 1e-6f);
        uint32_t c0p = h2pack(is0 * rot[c * DD + n], is1 * rot[(c + 1) * DD + n]);
        uint32_t c1p = h2pack(is8 * rot[(c + 8) * DD + n], is9 * rot[(c + 9) * DD + n]);
        ((uint2*)(sb + SM_B2))[u] = make_uint2(c0p, c1p);
    }
    if (tid < DD) sclp[tid] = scales[tid];

    float bn[7];
    #pragma unroll
    for (int q = 0; q < 7; ++q) bn[q] = 0.5f * (cent[q] + cent[q + 1]);
    // lane-distributed packed centroid: low16 = f16(c), high16 = f16(c - hi)
    uint32_t ccv2;
    {
        float cv = cent[lane & 7];
        __half ch = __float2half_rn(cv);
        __half cl = __float2half_rn(cv - __half2float(ch));
        ccv2 = ((uint32_t)__half_as_ushort(cl) << 16) | __half_as_ushort(ch);
    }

    __syncthreads();   // block barrier: B tables + scales ready

    const uint4* b1q = (const uint4*)(sb + SM_B1);
    const uint2* b2q = (const uint2*)(sb + SM_B2);
    char* zp = sb + SM_ZI + pair * 4224;          // pair-shared: 32 rows x 132B

    const long ctabase = (long)blockIdx.x * (ROWS_ITER * ITERS);

    for (int tt = 0; tt < ITERS; ++tt) {
        const long rowbase = ctabase + (long)tt * ROWS_ITER;

        // ---- GEMM1 (hi/lo fp16, 3 MMAs per k16 step) on RAW k; ssq fused ----
        float acc[2][8][4];
        #pragma unroll
        for (int i = 0; i < 2; ++i)
            #pragma unroll
            for (int j = 0; j < 8; ++j)
                #pragma unroll
                for (int p = 0; p < 4; ++p) acc[i][j][p] = 0.0f;

        float ssq[4] = {0.0f, 0.0f, 0.0f, 0.0f};
        {
            const float* kp0 = k + (rowbase + rp + g) * (long)DD;       // tile0 row g
            const float* kp1 = kp0 + 8 * DD;                            // tile0 row g+8
            const float* kp2 = kp0 + 16 * DD;                           // tile1 row g
            const float* kp3 = kp0 + 24 * DD;                           // tile1 row g+8

            #pragma unroll 2
            for (int ks = 0; ks < 8; ++ks) {
                int c0 = 16 * ks + 2 * t;
                float2 v00 = *(const float2*)&kp0[c0];
                float2 v01 = *(const float2*)&kp1[c0];
                float2 v08 = *(const float2*)&kp0[c0 + 8];
                float2 v09 = *(const float2*)&kp1[c0 + 8];
                float2 v10 = *(const float2*)&kp2[c0];
                float2 v11 = *(const float2*)&kp3[c0];
                float2 v18 = *(const float2*)&kp2[c0 + 8];
                float2 v19 = *(const float2*)&kp3[c0 + 8];
                ssq[0] += v00.x * v00.x + v00.y * v00.y + v08.x * v08.x + v08.y * v08.y;
                ssq[1] += v01.x * v01.x + v01.y * v01.y + v09.x * v09.x + v09.y * v09.y;
                ssq[2] += v10.x * v10.x + v10.y * v10.y + v18.x * v18.x + v18.y * v18.y;
                ssq[3] += v11.x * v11.x + v11.y * v11.y + v19.x * v19.x + v19.y * v19.y;

                uint32_t ah0[4], al0[4], ah1[4], al1[4];
                ah0[0] = h2pack(v00.x, v00.y);
                ah0[1] = h2pack(v01.x, v01.y);
                ah0[2] = h2pack(v08.x, v08.y);
                ah0[3] = h2pack(v09.x, v09.y);
                ah1[0] = h2pack(v10.x, v10.y);
                ah1[1] = h2pack(v11.x, v11.y);
                ah1[2] = h2pack(v18.x, v18.y);
                ah1[3] = h2pack(v19.x, v19.y);
                {
                    float2 h0 = h2unpack(ah0[0]), h1 = h2unpack(ah0[1]);
                    float2 h2 = h2unpack(ah0[2]), h3 = h2unpack(ah0[3]);
                    al0[0] = h2pack(v00.x - h0.x, v00.y - h0.y);
                    al0[1] = h2pack(v01.x - h1.x, v01.y - h1.y);
                    al0[2] = h2pack(v08.x - h2.x, v08.y - h2.y);
                    al0[3] = h2pack(v09.x - h3.x, v09.y - h3.y);
                }
                {
                    float2 h0 = h2unpack(ah1[0]), h1 = h2unpack(ah1[1]);
                    float2 h2 = h2unpack(ah1[2]), h3 = h2unpack(ah1[3]);
                    al1[0] = h2pack(v10.x - h0.x, v10.y - h0.y);
                    al1[1] = h2pack(v11.x - h1.x, v11.y - h1.y);
                    al1[2] = h2pack(v18.x - h2.x, v18.y - h2.y);
                    al1[3] = h2pack(v19.x - h3.x, v19.y - h3.y);
                }

                #pragma unroll
                for (int grp = 0; grp < 2; ++grp) {
                    uint4 bb[4];
                    #pragma unroll
                    for (int j = 0; j < 4; ++j)
                        bb[j] = b1q[(ks * 16 + nbase + grp * 4 + j) * 32 + lane];
                    #pragma unroll
                    for (int j = 0; j < 4; ++j) {
                        int j8 = grp * 4 + j;
                        mma16(acc[0][j8], ah0, bb[j].x, bb[j].y);   // hi*hi
                        mma16(acc[0][j8], al0, bb[j].x, bb[j].y);   // lo*hi
                        mma16(acc[0][j8], ah0, bb[j].z, bb[j].w);   // hi*lo
                        mma16(acc[1][j8], ah1, bb[j].x, bb[j].y);
                        mma16(acc[1][j8], al1, bb[j].x, bb[j].y);
                        mma16(acc[1][j8], ah1, bb[j].z, bb[j].w);
                    }
                }
            }
        }

        // ---- norms (warp-private; from raw k, summed over the 4 t-lanes) ----
        float nrm[4], inv[4];
        #pragma unroll
        for (int i = 0; i < 4; ++i) {
            float s = ssq[i];
            s += __shfl_xor_sync(0xffffffffu, s, 1);
            s += __shfl_xor_sync(0xffffffffu, s, 2);
            nrm[i] = sqrtf(s);
            inv[i] = 1.0f / (nrm[i] + 1e-10f);
        }

        // ---- prefetch next iteration's k toward L2 ----
        if (tt + 1 < ITERS) {
            const char* np = (const char*)(k + (rowbase + ROWS_ITER) * (long)DD);
            #pragma unroll
            for (int pf = 0; pf < 2; ++pf)
                asm volatile("prefetch.global.L2 [%0];"
                             :: "l"(np + (pf * NTHREADS + tid) * 128));
        }

        // ---- pair barrier A: partner done reading ZI (prev iter GEMM2) ----
        asm volatile("bar.sync %0, 64;" :: "r"(pair + 1) : "memory");

        // ---- epilogue 1: scale*invnorm -> bucketize -> byte indices to ZI ----
        {
            const float2* scl2 = (const float2*)(sb + SM_SCL);
            #pragma unroll
            for (int i = 0; i < 2; ++i) {
                #pragma unroll
                for (int j8 = 0; j8 < 8; ++j8) {
                    int c = 8 * (nbase + j8) + 2 * t;
                    float2 sc = scl2[c >> 1];
                    float f0 = acc[i][j8][0] * sc.x * inv[2 * i];
                    float f1 = acc[i][j8][1] * sc.y * inv[2 * i];
                    float f2 = acc[i][j8][2] * sc.x * inv[2 * i + 1];
                    float f3 = acc[i][j8][3] * sc.y * inv[2 * i + 1];
                    int i0 = 0, i1 = 0, i2 = 0, i3 = 0;
                    #pragma unroll
                    for (int q = 0; q < 7; ++q) {
                        i0 += (f0 > bn[q]); i1 += (f1 > bn[q]);
                        i2 += (f2 > bn[q]); i3 += (f3 > bn[q]);
                    }
                    int lr = 16 * i + g;
                    *(uint16_t*)(zp + lr * 132 + c)       = (uint16_t)(i0 | (i1 << 8));
                    *(uint16_t*)(zp + (lr + 8) * 132 + c) = (uint16_t)(i2 | (i3 << 8));
                }
            }
        }

        // ---- pair barrier B: both warps' ZI written before GEMM2 reads ----
        asm volatile("bar.sync %0, 64;" :: "r"(pair + 1) : "memory");

        // ---- GEMM2 (zh/zl decoded from ZI via packed-centroid shfl) ----
        #pragma unroll
        for (int i = 0; i < 2; ++i)
            #pragma unroll
            for (int j = 0; j < 8; ++j)
                #pragma unroll
                for (int p = 0; p < 4; ++p) acc[i][j][p] = 0.0f;

        {
            #pragma unroll 2
            for (int ks = 0; ks < 8; ++ks) {
                int c0 = 16 * ks + 2 * t;
                uint32_t zh0[4], zl0[4], zh1[4], zl1[4];
                #pragma unroll
                for (int i = 0; i < 2; ++i) {
                    int lr = 16 * i + g;
                    uint32_t u0 = *(const uint16_t*)(zp + lr * 132 + c0);
                    uint32_t u1 = *(const uint16_t*)(zp + (lr + 8) * 132 + c0);
                    uint32_t u2 = *(const uint16_t*)(zp + lr * 132 + c0 + 8);
                    uint32_t u3 = *(const uint16_t*)(zp + (lr + 8) * 132 + c0 + 8);
                    uint32_t p00 = __shfl_sync(0xffffffffu, ccv2, u0 & 0xff);
                    uint32_t p01 = __shfl_sync(0xffffffffu, ccv2, u0 >> 8);
                    uint32_t p10 = __shfl_sync(0xffffffffu, ccv2, u1 & 0xff);
                    uint32_t p11 = __shfl_sync(0xffffffffu, ccv2, u1 >> 8);
                    uint32_t p20 = __shfl_sync(0xffffffffu, ccv2, u2 & 0xff);
                    uint32_t p21 = __shfl_sync(0xffffffffu, ccv2, u2 >> 8);
                    uint32_t p30 = __shfl_sync(0xffffffffu, ccv2, u3 & 0xff);
                    uint32_t p31 = __shfl_sync(0xffffffffu, ccv2, u3 >> 8);
                    uint32_t* zh = i ? zh1 : zh0;
                    uint32_t* zl = i ? zl1 : zl0;
                    zh[0] = __byte_perm(p00, p01, 0x5410);
                    zl[0] = __byte_perm(p00, p01, 0x7632);
                    zh[1] = __byte_perm(p10, p11, 0x5410);
                    zl[1] = __byte_perm(p10, p11, 0x7632);
                    zh[2] = __byte_perm(p20, p21, 0x5410);
                    zl[2] = __byte_perm(p20, p21, 0x7632);
                    zh[3] = __byte_perm(p30, p31, 0x5410);
                    zl[3] = __byte_perm(p30, p31, 0x7632);
                }

                #pragma unroll
                for (int grp = 0; grp < 2; ++grp) {
                    uint2 cb[4];
                    #pragma unroll
                    for (int j = 0; j < 4; ++j)
                        cb[j] = b2q[(ks * 16 + nbase + grp * 4 + j) * 32 + lane];
                    #pragma unroll
                    for (int j = 0; j < 4; ++j) {
                        int j8 = grp * 4 + j;
                        mma16(acc[0][j8], zh0, cb[j].x, cb[j].y);
                        mma16(acc[0][j8], zl0, cb[j].x, cb[j].y);
                        mma16(acc[1][j8], zh1, cb[j].x, cb[j].y);
                        mma16(acc[1][j8], zl1, cb[j].x, cb[j].y);
                    }
                }
            }
        }

        // ---- epilogue 2: x norm, store ----
        #pragma unroll
        for (int i = 0; i < 2; ++i) {
            float* o0 = out + (rowbase + rp + 16 * i + g) * (long)DD;
            float* o1 = o0 + 8 * DD;
            float n0 = nrm[2 * i], n1 = nrm[2 * i + 1];
            #pragma unroll
            for (int j8 = 0; j8 < 8; ++j8) {
                int c = 8 * (nbase + j8) + 2 * t;
                *(float2*)(o0 + c) = make_float2(acc[i][j8][0] * n0, acc[i][j8][1] * n0);
                *(float2*)(o1 + c) = make_float2(acc[i][j8][2] * n1, acc[i][j8][3] * n1);
            }
        }
    }
}

extern "C" void kernel_launch(void* const* d_in, const int* in_sizes, int n_in,
                              void* d_out, int out_size) {
    const float* k      = (const float*)d_in[0];
    const float* rot    = (const float*)d_in[1];
    const float* scales = (const float*)d_in[2];
    const float* cent   = (const float*)d_in[3];
    float* out = (float*)d_out;

    int nrows = in_sizes[0] / DD;
    int nblocks = nrows / (ROWS_ITER * ITERS);   // 1048576 / 1024 = 1024

    cudaFuncSetAttribute(rotadapt_mma_kernel,
                         cudaFuncAttributeMaxDynamicSharedMemorySize, SMEM_BYTES);
    rotadapt_mma_kernel<<<nblocks, NTHREADS, SMEM_BYTES>>>(k, rot, scales, cent, out);
}

// round 16
// speedup vs baseline: 1.5220x; 1.0485x over previous
#include <cuda_runtime.h>
#include <cuda_fp16.h>
#include <cstdint>

#define DD 128
#define ROWS_ITER 256        // rows per CTA iteration (16 per warp)
#define ITERS 4              // iterations per CTA -> 1024 rows/CTA
#define NTHREADS 512

// ---- smem byte offsets ----
#define SM_B1   0            // GEMM1 B: uint4 {bh0,bh1,bl0,bl1} f16x2 frags (64KB)
#define SM_B2   65536        // GEMM2 B: uint2 f16x2 (iscl*R) frags (32KB)
#define SM_ZL   98304        // z lo-parts, thread-private: 16 warps x 4KB (64KB)
#define SM_SCL  163840       // 128 f32
#define SMEM_BYTES 164352

// D += A(f16) * B(f16), m16n8k16, fp32 accumulate
__device__ __forceinline__ void mma16(float d[4], const uint32_t a[4],
                                      uint32_t b0, uint32_t b1) {
    asm volatile(
        "mma.sync.aligned.m16n8k16.row.col.f32.f16.f16.f32 "
        "{%0,%1,%2,%3}, {%4,%5,%6,%7}, {%8,%9}, {%0,%1,%2,%3};"
        : "+f"(d[0]), "+f"(d[1]), "+f"(d[2]), "+f"(d[3])
        : "r"(a[0]), "r"(a[1]), "r"(a[2]), "r"(a[3]), "r"(b0), "r"(b1));
}

__device__ __forceinline__ uint32_t h2pack(float a, float b) {
    __half2 h = __floats2half2_rn(a, b);
    return *(uint32_t*)&h;
}
__device__ __forceinline__ float2 h2unpack(uint32_t u) {
    __half2 h = *(__half2*)&u;
    return __half22float2(h);
}

extern "C" __global__ void __launch_bounds__(NTHREADS, 1)
rotadapt_mma_kernel(const float* __restrict__ k,
                    const float* __restrict__ rot,
                    const float* __restrict__ scales,
                    const float* __restrict__ cent,
                    float* __restrict__ out)
{
    extern __shared__ char sb[];
    float* sclp = (float*)(sb + SM_SCL);

    const int tid  = threadIdx.x;
    const int lane = tid & 31, w = tid >> 5;      // 16 warps
    const int g = lane >> 2, t = lane & 3;
    const int rA = 16 * w + g;                    // warp owns rows [16w, 16w+16)

    // ---- prologue: build f16 fragment tables ----
    for (int u = tid; u < 8 * 16 * 32; u += NTHREADS) {
        int ln = u & 31, nt = (u >> 5) & 15, ks = u >> 9;
        int gg = ln >> 2, t2 = ln & 3;
        int n = 8 * nt + gg;
        int c = 16 * ks + 2 * t2;
        float r0 = rot[n * DD + c],     r1 = rot[n * DD + c + 1];
        float r2 = rot[n * DD + c + 8], r3 = rot[n * DD + c + 9];
        uint32_t bh0 = h2pack(r0, r1);
        uint32_t bh1 = h2pack(r2, r3);
        float2 h01 = h2unpack(bh0);
        float2 h23 = h2unpack(bh1);
        uint32_t bl0 = h2pack(r0 - h01.x, r1 - h01.y);
        uint32_t bl1 = h2pack(r2 - h23.x, r3 - h23.y);
        ((uint4*)(sb + SM_B1))[u] = make_uint4(bh0, bh1, bl0, bl1);
        float is0 = 1.0f / fmaxf(scales[c],     1e-6f);
        float is1 = 1.0f / fmaxf(scales[c + 1], 1e-6f);
        float is8 = 1.0f / fmaxf(scales[c + 8], 1e-6f);
        float is9 = 1.0f / fmaxf(scales[c + 9], 1e-6f);
        uint32_t c0p = h2pack(is0 * rot[c * DD + n], is1 * rot[(c + 1) * DD + n]);
        uint32_t c1p = h2pack(is8 * rot[(c + 8) * DD + n], is9 * rot[(c + 9) * DD + n]);
        ((uint2*)(sb + SM_B2))[u] = make_uint2(c0p, c1p);
    }
    if (tid < DD) sclp[tid] = scales[tid];

    float bn[7];
    #pragma unroll
    for (int q = 0; q < 7; ++q) bn[q] = 0.5f * (cent[q] + cent[q + 1]);
    // packed centroid: low16 = f16(cent), high16 = f16(cent - hi)
    uint32_t centpk[8];
    #pragma unroll
    for (int q = 0; q < 8; ++q) {
        float cv = cent[q];
        __half ch = __float2half_rn(cv);
        __half cl = __float2half_rn(cv - __half2float(ch));
        centpk[q] = ((uint32_t)__half_as_ushort(cl) << 16) | __half_as_ushort(ch);
    }

    __syncthreads();   // the ONLY block barrier: B tables + scales ready

    const uint4* b1q = (const uint4*)(sb + SM_B1);
    const uint2* b2q = (const uint2*)(sb + SM_B2);
    // thread-private zl slots: warp block 4KB, lane*8, nt stride 256B
    uint2* zlp = (uint2*)(sb + SM_ZL + w * 4096 + lane * 8);

    const long ctabase = (long)blockIdx.x * (ROWS_ITER * ITERS);

    for (int tt = 0; tt < ITERS; ++tt) {
        const long rowbase = ctabase + (long)tt * ROWS_ITER;

        // ---- GEMM1 (hi/lo fp16, 3 MMAs per k16 step) on RAW k ----
        float acc[16][4];
        #pragma unroll
        for (int nt = 0; nt < 16; ++nt)
            #pragma unroll
            for (int p = 0; p < 4; ++p) acc[nt][p] = 0.0f;

        {
            const float* k0 = k + (rowbase + rA) * (long)DD;
            const float* k1 = k0 + 8 * DD;

            #pragma unroll 2
            for (int ks = 0; ks < 8; ++ks) {
                int c0 = 16 * ks + 2 * t;
                float2 v00 = *(const float2*)&k0[c0];
                float2 v10 = *(const float2*)&k1[c0];
                float2 v08 = *(const float2*)&k0[c0 + 8];
                float2 v18 = *(const float2*)&k1[c0 + 8];
                uint32_t ah[4], al[4];
                ah[0] = h2pack(v00.x, v00.y);
                ah[1] = h2pack(v10.x, v10.y);
                ah[2] = h2pack(v08.x, v08.y);
                ah[3] = h2pack(v18.x, v18.y);
                float2 h0 = h2unpack(ah[0]), h1 = h2unpack(ah[1]);
                float2 h2 = h2unpack(ah[2]), h3 = h2unpack(ah[3]);
                al[0] = h2pack(v00.x - h0.x, v00.y - h0.y);
                al[1] = h2pack(v10.x - h1.x, v10.y - h1.y);
                al[2] = h2pack(v08.x - h2.x, v08.y - h2.y);
                al[3] = h2pack(v18.x - h3.x, v18.y - h3.y);

                uint4 bb[2][4];
                #pragma unroll
                for (int j = 0; j < 4; ++j)
                    bb[0][j] = b1q[(ks * 16 + j) * 32 + lane];
                #pragma unroll
                for (int grp = 0; grp < 4; ++grp) {
                    const int cur = grp & 1, nxt = cur ^ 1;
                    if (grp < 3) {
                        #pragma unroll
                        for (int j = 0; j < 4; ++j)
                            bb[nxt][j] = b1q[(ks * 16 + (grp + 1) * 4 + j) * 32 + lane];
                    }
                    #pragma unroll
                    for (int j = 0; j < 4; ++j) {
                        int nt = grp * 4 + j;
                        mma16(acc[nt], ah, bb[cur][j].x, bb[cur][j].y);   // hi*hi
                        mma16(acc[nt], al, bb[cur][j].x, bb[cur][j].y);   // lo*hi
                        mma16(acc[nt], ah, bb[cur][j].z, bb[cur][j].w);   // hi*lo
                    }
                }
            }
        }

        // ---- norms from acc: R orthogonal => ||k @ R^T|| = ||k|| ----
        float nrm0, nrm1, inv0, inv1;
        {
            float ssq0 = 0.0f, ssq1 = 0.0f;
            #pragma unroll
            for (int nt = 0; nt < 16; ++nt) {
                ssq0 += acc[nt][0] * acc[nt][0] + acc[nt][1] * acc[nt][1];
                ssq1 += acc[nt][2] * acc[nt][2] + acc[nt][3] * acc[nt][3];
            }
            ssq0 += __shfl_xor_sync(0xffffffffu, ssq0, 1);
            ssq0 += __shfl_xor_sync(0xffffffffu, ssq0, 2);
            ssq1 += __shfl_xor_sync(0xffffffffu, ssq1, 1);
            ssq1 += __shfl_xor_sync(0xffffffffu, ssq1, 2);
            nrm0 = sqrtf(ssq0);
            nrm1 = sqrtf(ssq1);
            inv0 = 1.0f / (nrm0 + 1e-10f);
            inv1 = 1.0f / (nrm1 + 1e-10f);
        }

        // ---- prefetch next iteration's k toward L2 ----
        if (tt + 1 < ITERS) {
            const char* np = (const char*)(k + (rowbase + ROWS_ITER) * (long)DD);
            #pragma unroll
            for (int pf = 0; pf < 2; ++pf)
                asm volatile("prefetch.global.L2 [%0];"
                             :: "l"(np + (pf * NTHREADS + tid) * 128));
        }

        // ---- epilogue 1: bucketize-select packed f16 centroids ----
        // zh -> dedicated 32-reg array (NOT acc); zl -> thread-private smem
        uint32_t zhreg[16][2];
        {
            const float2* scl2 = (const float2*)(sb + SM_SCL);
            #pragma unroll
            for (int nt = 0; nt < 16; ++nt) {
                float2 sc = scl2[(8 * nt + 2 * t) >> 1];
                float f0 = acc[nt][0] * sc.x * inv0, f1 = acc[nt][1] * sc.y * inv0;
                float f2 = acc[nt][2] * sc.x * inv1, f3 = acc[nt][3] * sc.y * inv1;
                uint32_t z0 = centpk[0], z1 = centpk[0], z2 = centpk[0], z3 = centpk[0];
                #pragma unroll
                for (int q = 0; q < 7; ++q) {
                    z0 = (f0 > bn[q]) ? centpk[q + 1] : z0;
                    z1 = (f1 > bn[q]) ? centpk[q + 1] : z1;
                    z2 = (f2 > bn[q]) ? centpk[q + 1] : z2;
                    z3 = (f3 > bn[q]) ? centpk[q + 1] : z3;
                }
                zhreg[nt][0] = __byte_perm(z0, z1, 0x5410);
                zhreg[nt][1] = __byte_perm(z2, z3, 0x5410);
                uint32_t ul01 = __byte_perm(z0, z1, 0x7632);
                uint32_t ul23 = __byte_perm(z2, z3, 0x7632);
                zlp[nt * 32] = make_uint2(ul01, ul23);   // same-thread, no sync needed
            }
        }

        // ---- GEMM2 (zh from zhreg + zl from smem): REUSE acc registers ----
        #pragma unroll
        for (int nt = 0; nt < 16; ++nt)
            #pragma unroll
            for (int p = 0; p < 4; ++p) acc[nt][p] = 0.0f;

        {
            #pragma unroll 2
            for (int ks = 0; ks < 8; ++ks) {
                uint32_t zh[4] = { zhreg[2 * ks][0],     zhreg[2 * ks][1],
                                   zhreg[2 * ks + 1][0], zhreg[2 * ks + 1][1] };
                uint2 la = zlp[(2 * ks) * 32];
                uint2 lb = zlp[(2 * ks + 1) * 32];
                uint32_t zl[4] = { la.x, la.y, lb.x, lb.y };

                uint2 cb[2][4];
                #pragma unroll
                for (int j = 0; j < 4; ++j)
                    cb[0][j] = b2q[(ks * 16 + j) * 32 + lane];
                #pragma unroll
                for (int grp = 0; grp < 4; ++grp) {
                    const int cur = grp & 1, nxt = cur ^ 1;
                    if (grp < 3) {
                        #pragma unroll
                        for (int j = 0; j < 4; ++j)
                            cb[nxt][j] = b2q[(ks * 16 + (grp + 1) * 4 + j) * 32 + lane];
                    }
                    #pragma unroll
                    for (int j = 0; j < 4; ++j) {
                        int nt = grp * 4 + j;
                        mma16(acc[nt], zh, cb[cur][j].x, cb[cur][j].y);
                        mma16(acc[nt], zl, cb[cur][j].x, cb[cur][j].y);
                    }
                }
            }
        }

        // ---- epilogue 2: x norm, store ----
        {
            float* o0 = out + (rowbase + rA) * (long)DD;
            float* o1 = o0 + 8 * DD;
            #pragma unroll
            for (int nt = 0; nt < 16; ++nt) {
                int c = 8 * nt + 2 * t;
                *(float2*)(o0 + c) = make_float2(acc[nt][0] * nrm0, acc[nt][1] * nrm0);
                *(float2*)(o1 + c) = make_float2(acc[nt][2] * nrm1, acc[nt][3] * nrm1);
            }
        }
    }
}

extern "C" void kernel_launch(void* const* d_in, const int* in_sizes, int n_in,
                              void* d_out, int out_size) {
    const float* k      = (const float*)d_in[0];
    const float* rot    = (const float*)d_in[1];
    const float* scales = (const float*)d_in[2];
    const float* cent   = (const float*)d_in[3];
    float* out = (float*)d_out;

    int nrows = in_sizes[0] / DD;
    int nblocks = nrows / (ROWS_ITER * ITERS);   // 1048576 / 1024 = 1024

    cudaFuncSetAttribute(rotadapt_mma_kernel,
                         cudaFuncAttributeMaxDynamicSharedMemorySize, SMEM_BYTES);
    rotadapt_mma_kernel<<<nblocks, NTHREADS, SMEM_BYTES>>>(k, rot, scales, cent, out);
}

// round 17
// speedup vs baseline: 1.8152x; 1.1926x over previous
#include <cuda_runtime.h>
#include <cuda_fp16.h>
#include <cstdint>

#define DD 128
#define ROWS_ITER 256        // rows per CTA iteration (16 per warp)
#define ITERS 4              // iterations per CTA -> 1024 rows/CTA
#define NTHREADS 512

// ---- smem byte offsets ----
#define SM_B1   0            // GEMM1 B: uint4 {bh0,bh1,bl0,bl1} f16x2 frags (64KB)
#define SM_B2   65536        // GEMM2 B: uint2 f16x2 (iscl*R) frags (32KB)
#define SM_ZQ   98304        // z hi f16 pairs, thread-private slots (64KB)
#define SM_SCL  163840       // 128 f32
#define SMEM_BYTES 164352

// D += A(f16) * B(f16), m16n8k16, fp32 accumulate
__device__ __forceinline__ void mma16(float d[4], const uint32_t a[4],
                                      uint32_t b0, uint32_t b1) {
    asm volatile(
        "mma.sync.aligned.m16n8k16.row.col.f32.f16.f16.f32 "
        "{%0,%1,%2,%3}, {%4,%5,%6,%7}, {%8,%9}, {%0,%1,%2,%3};"
        : "+f"(d[0]), "+f"(d[1]), "+f"(d[2]), "+f"(d[3])
        : "r"(a[0]), "r"(a[1]), "r"(a[2]), "r"(a[3]), "r"(b0), "r"(b1));
}

__device__ __forceinline__ uint32_t h2pack(float a, float b) {
    __half2 h = __floats2half2_rn(a, b);
    return *(uint32_t*)&h;
}
__device__ __forceinline__ float2 h2unpack(uint32_t u) {
    __half2 h = *(__half2*)&u;
    return __half22float2(h);
}

extern "C" __global__ void __launch_bounds__(NTHREADS, 1)
rotadapt_mma_kernel(const float* __restrict__ k,
                    const float* __restrict__ rot,
                    const float* __restrict__ scales,
                    const float* __restrict__ cent,
                    float* __restrict__ out)
{
    extern __shared__ char sb[];
    float* sclp = (float*)(sb + SM_SCL);

    const int tid  = threadIdx.x;
    const int lane = tid & 31, w = tid >> 5;      // 16 warps
    const int g = lane >> 2, t = lane & 3;
    const int rA = 16 * w + g;                    // warp owns rows [16w, 16w+16)

    // ---- prologue: build f16 fragment tables ----
    for (int u = tid; u < 8 * 16 * 32; u += NTHREADS) {
        int ln = u & 31, nt = (u >> 5) & 15, ks = u >> 9;
        int gg = ln >> 2, t2 = ln & 3;
        int n = 8 * nt + gg;
        int c = 16 * ks + 2 * t2;
        float r0 = rot[n * DD + c],     r1 = rot[n * DD + c + 1];
        float r2 = rot[n * DD + c + 8], r3 = rot[n * DD + c + 9];
        uint32_t bh0 = h2pack(r0, r1);
        uint32_t bh1 = h2pack(r2, r3);
        float2 h01 = h2unpack(bh0);
        float2 h23 = h2unpack(bh1);
        uint32_t bl0 = h2pack(r0 - h01.x, r1 - h01.y);
        uint32_t bl1 = h2pack(r2 - h23.x, r3 - h23.y);
        ((uint4*)(sb + SM_B1))[u] = make_uint4(bh0, bh1, bl0, bl1);
        float is0 = 1.0f / fmaxf(scales[c],     1e-6f);
        float is1 = 1.0f / fmaxf(scales[c + 1], 1e-6f);
        float is8 = 1.0f / fmaxf(scales[c + 8], 1e-6f);
        float is9 = 1.0f / fmaxf(scales[c + 9], 1e-6f);
        uint32_t c0p = h2pack(is0 * rot[c * DD + n], is1 * rot[(c + 1) * DD + n]);
        uint32_t c1p = h2pack(is8 * rot[(c + 8) * DD + n], is9 * rot[(c + 9) * DD + n]);
        ((uint2*)(sb + SM_B2))[u] = make_uint2(c0p, c1p);
    }
    if (tid < DD) sclp[tid] = scales[tid];

    float bn[7];
    #pragma unroll
    for (int q = 0; q < 7; ++q) bn[q] = 0.5f * (cent[q] + cent[q + 1]);
    // packed centroid: f16(cent) in low 16 bits
    uint32_t centpk[8];
    #pragma unroll
    for (int q = 0; q < 8; ++q)
        centpk[q] = (uint32_t)__half_as_ushort(__float2half_rn(cent[q]));

    __syncthreads();   // the ONLY block barrier: B tables + scales ready

    const uint4* b1q = (const uint4*)(sb + SM_B1);
    const uint2* b2q = (const uint2*)(sb + SM_B2);
    // thread-private zh slots: warp 4KB block; slot p (=ks) at p*512 + lane*16
    char* zqp = sb + SM_ZQ + w * 4096 + lane * 16;

    const long ctabase = (long)blockIdx.x * (ROWS_ITER * ITERS);

    for (int tt = 0; tt < ITERS; ++tt) {
        const long rowbase = ctabase + (long)tt * ROWS_ITER;

        // ---- GEMM1 (hi/lo fp16, 3 MMAs per k16 step) on RAW k ----
        float acc[16][4];
        #pragma unroll
        for (int nt = 0; nt < 16; ++nt)
            #pragma unroll
            for (int p = 0; p < 4; ++p) acc[nt][p] = 0.0f;

        {
            const float* k0 = k + (rowbase + rA) * (long)DD;
            const float* k1 = k0 + 8 * DD;

            #pragma unroll 2
            for (int ks = 0; ks < 8; ++ks) {
                int c0 = 16 * ks + 2 * t;
                float2 v00 = *(const float2*)&k0[c0];
                float2 v10 = *(const float2*)&k1[c0];
                float2 v08 = *(const float2*)&k0[c0 + 8];
                float2 v18 = *(const float2*)&k1[c0 + 8];
                uint32_t ah[4], al[4];
                ah[0] = h2pack(v00.x, v00.y);
                ah[1] = h2pack(v10.x, v10.y);
                ah[2] = h2pack(v08.x, v08.y);
                ah[3] = h2pack(v18.x, v18.y);
                float2 h0 = h2unpack(ah[0]), h1 = h2unpack(ah[1]);
                float2 h2 = h2unpack(ah[2]), h3 = h2unpack(ah[3]);
                al[0] = h2pack(v00.x - h0.x, v00.y - h0.y);
                al[1] = h2pack(v10.x - h1.x, v10.y - h1.y);
                al[2] = h2pack(v08.x - h2.x, v08.y - h2.y);
                al[3] = h2pack(v18.x - h3.x, v18.y - h3.y);

                uint4 bb[2][4];
                #pragma unroll
                for (int j = 0; j < 4; ++j)
                    bb[0][j] = b1q[(ks * 16 + j) * 32 + lane];
                #pragma unroll
                for (int grp = 0; grp < 4; ++grp) {
                    const int cur = grp & 1, nxt = cur ^ 1;
                    if (grp < 3) {
                        #pragma unroll
                        for (int j = 0; j < 4; ++j)
                            bb[nxt][j] = b1q[(ks * 16 + (grp + 1) * 4 + j) * 32 + lane];
                    }
                    #pragma unroll
                    for (int j = 0; j < 4; ++j) {
                        int nt = grp * 4 + j;
                        mma16(acc[nt], ah, bb[cur][j].x, bb[cur][j].y);   // hi*hi
                        mma16(acc[nt], al, bb[cur][j].x, bb[cur][j].y);   // lo*hi
                        mma16(acc[nt], ah, bb[cur][j].z, bb[cur][j].w);   // hi*lo
                    }
                }
            }
        }

        // ---- norms from acc: R orthogonal => ||k @ R^T|| = ||k|| ----
        float nrm0, nrm1, inv0, inv1;
        {
            float ssq0 = 0.0f, ssq1 = 0.0f;
            #pragma unroll
            for (int nt = 0; nt < 16; ++nt) {
                ssq0 += acc[nt][0] * acc[nt][0] + acc[nt][1] * acc[nt][1];
                ssq1 += acc[nt][2] * acc[nt][2] + acc[nt][3] * acc[nt][3];
            }
            ssq0 += __shfl_xor_sync(0xffffffffu, ssq0, 1);
            ssq0 += __shfl_xor_sync(0xffffffffu, ssq0, 2);
            ssq1 += __shfl_xor_sync(0xffffffffu, ssq1, 1);
            ssq1 += __shfl_xor_sync(0xffffffffu, ssq1, 2);
            nrm0 = sqrtf(ssq0);
            nrm1 = sqrtf(ssq1);
            inv0 = 1.0f / (nrm0 + 1e-10f);
            inv1 = 1.0f / (nrm1 + 1e-10f);
        }

        // ---- prefetch next iteration's k toward L2 ----
        if (tt + 1 < ITERS) {
            const char* np = (const char*)(k + (rowbase + ROWS_ITER) * (long)DD);
            #pragma unroll
            for (int pf = 0; pf < 2; ++pf)
                asm volatile("prefetch.global.L2 [%0];"
                             :: "l"(np + (pf * NTHREADS + tid) * 128));
        }

        // ---- epilogue 1: bucketize -> select f16 centroid -> zh pairs to smem ----
        // slot p(=ks) holds uint4 {zh01[2p], zh23[2p], zh01[2p+1], zh23[2p+1]}
        {
            const float2* scl2 = (const float2*)(sb + SM_SCL);
            #pragma unroll
            for (int nt = 0; nt < 16; ++nt) {
                float2 sc = scl2[(8 * nt + 2 * t) >> 1];
                float f0 = acc[nt][0] * sc.x * inv0, f1 = acc[nt][1] * sc.y * inv0;
                float f2 = acc[nt][2] * sc.x * inv1, f3 = acc[nt][3] * sc.y * inv1;
                uint32_t z0 = centpk[0], z1 = centpk[0], z2 = centpk[0], z3 = centpk[0];
                #pragma unroll
                for (int q = 0; q < 7; ++q) {
                    z0 = (f0 > bn[q]) ? centpk[q + 1] : z0;
                    z1 = (f1 > bn[q]) ? centpk[q + 1] : z1;
                    z2 = (f2 > bn[q]) ? centpk[q + 1] : z2;
                    z3 = (f3 > bn[q]) ? centpk[q + 1] : z3;
                }
                uint32_t zh01 = __byte_perm(z0, z1, 0x5410);
                uint32_t zh23 = __byte_perm(z2, z3, 0x5410);
                // even nt -> slot offset 0, odd nt -> offset 8 (same-thread, no sync)
                *(uint2*)(zqp + (nt >> 1) * 512 + (nt & 1) * 8) = make_uint2(zh01, zh23);
            }
        }

        // ---- GEMM2 (single-pass fp16 z, 1 MMA per nt per k16): reuse acc ----
        #pragma unroll
        for (int nt = 0; nt < 16; ++nt)
            #pragma unroll
            for (int p = 0; p < 4; ++p) acc[nt][p] = 0.0f;

        {
            #pragma unroll 2
            for (int ks = 0; ks < 8; ++ks) {
                uint4 zq = *(const uint4*)(zqp + ks * 512);
                uint32_t zh[4] = { zq.x, zq.y, zq.z, zq.w };

                uint2 cb[2][4];
                #pragma unroll
                for (int j = 0; j < 4; ++j)
                    cb[0][j] = b2q[(ks * 16 + j) * 32 + lane];
                #pragma unroll
                for (int grp = 0; grp < 4; ++grp) {
                    const int cur = grp & 1, nxt = cur ^ 1;
                    if (grp < 3) {
                        #pragma unroll
                        for (int j = 0; j < 4; ++j)
                            cb[nxt][j] = b2q[(ks * 16 + (grp + 1) * 4 + j) * 32 + lane];
                    }
                    #pragma unroll
                    for (int j = 0; j < 4; ++j) {
                        int nt = grp * 4 + j;
                        mma16(acc[nt], zh, cb[cur][j].x, cb[cur][j].y);
                    }
                }
            }
        }

        // ---- epilogue 2: x norm, store ----
        {
            float* o0 = out + (rowbase + rA) * (long)DD;
            float* o1 = o0 + 8 * DD;
            #pragma unroll
            for (int nt = 0; nt < 16; ++nt) {
                int c = 8 * nt + 2 * t;
                *(float2*)(o0 + c) = make_float2(acc[nt][0] * nrm0, acc[nt][1] * nrm0);
                *(float2*)(o1 + c) = make_float2(acc[nt][2] * nrm1, acc[nt][3] * nrm1);
            }
        }
    }
}

extern "C" void kernel_launch(void* const* d_in, const int* in_sizes, int n_in,
                              void* d_out, int out_size) {
    const float* k      = (const float*)d_in[0];
    const float* rot    = (const float*)d_in[1];
    const float* scales = (const float*)d_in[2];
    const float* cent   = (const float*)d_in[3];
    float* out = (float*)d_out;

    int nrows = in_sizes[0] / DD;
    int nblocks = nrows / (ROWS_ITER * ITERS);   // 1048576 / 1024 = 1024

    cudaFuncSetAttribute(rotadapt_mma_kernel,
                         cudaFuncAttributeMaxDynamicSharedMemorySize, SMEM_BYTES);
    rotadapt_mma_kernel<<<nblocks, NTHREADS, SMEM_BYTES>>>(k, rot, scales, cent, out);
}